// round 12
// baseline (speedup 1.0000x reference)
#include <cuda_runtime.h>

#define NTH   512
#define D_IN  2048
#define T_TOT 1000
#define NB    20

__device__ __forceinline__ float warp_red_min(float v) {
    #pragma unroll
    for (int o = 16; o; o >>= 1) v = fminf(v, __shfl_xor_sync(0xffffffffu, v, o));
    return v;
}
__device__ __forceinline__ float warp_red_max(float v) {
    #pragma unroll
    for (int o = 16; o; o >>= 1) v = fmaxf(v, __shfl_xor_sync(0xffffffffu, v, o));
    return v;
}

__global__ void __launch_bounds__(NTH, 1)
chaosfex_kernel(const float* __restrict__ x, float* __restrict__ out)
{
    // per-thread-private histogram counters, bank-conflict-free layout:
    // hist[bin*512 + tid] -> bank = tid % 32
    __shared__ int   hist[NB * NTH];          // 40 KB
    __shared__ float redmin[16], redmax[16];
    __shared__ float s_min, s_max;

    const int b   = blockIdx.x;
    const int tid = threadIdx.x;
    const float* row = x + b * D_IN;

    #pragma unroll
    for (int j = 0; j < NB; j++) hist[j * NTH + tid] = 0;

    // ---- row min/max (exact regardless of order) ----
    float v0 = row[tid], v1 = row[tid + 512], v2 = row[tid + 1024], v3 = row[tid + 1536];
    float vmin = fminf(fminf(v0, v1), fminf(v2, v3));
    float vmax = fmaxf(fmaxf(v0, v1), fmaxf(v2, v3));
    vmin = warp_red_min(vmin);
    vmax = warp_red_max(vmax);
    const int wid = tid >> 5, lid = tid & 31;
    if (lid == 0) { redmin[wid] = vmin; redmax[wid] = vmax; }
    __syncthreads();
    if (wid == 0) {
        float a  = redmin[lid & 15];
        float mx = redmax[lid & 15];
        #pragma unroll
        for (int o = 8; o; o >>= 1) {
            a  = fminf(a,  __shfl_xor_sync(0xffffffffu, a,  o));
            mx = fmaxf(mx, __shfl_xor_sync(0xffffffffu, mx, o));
        }
        if (lid == 0) { s_min = a; s_max = mx; }
    }
    __syncthreads();
    const float xmin = s_min, xmax = s_max;

    // ---- initial condition: RECIPROCAL-MULTIPLY normalize (fast-math LICM/arcp
    //      lowering of the broadcast divide), then clip ----
    const int nidx = (tid == 511) ? 2047 : (int)((double)tid * (2047.0 / 511.0));
    const float xi = row[nidx];
    const float denomn = __fadd_rn(__fsub_rn(xmax, xmin), 1e-10f);
    const float rden  = __fdiv_rn(1.0f, denomn);            // hoisted rn reciprocal
    const float xn    = __fmul_rn(__fsub_rn(xi, xmin), rden);
    float s = fminf(fmaxf(xn, 0.01f), 0.99f);

    // ---- trajectory features ----
    float acc   = __fmul_rn(s, s);      // me accumulator (step 0)
    int   cnt   = 0;
    int   first = 1 << 30;
    int   last  = -1;
    bool  prev  = s > 0.5f;

    {
        int bin0 = min(max((int)__fmul_rn(s, 20.0f), 0), 19);
        hist[bin0 * NTH + tid] += 1;
    }

    // Map variant B (CPU fast-math FMA contraction):
    //   m   = rn(0.1f * s)
    //   sum = fma(m, s, s)
    //   mod 1 == conditional subtract (exact for x in [0,1.1))
    #pragma unroll 4
    for (int t = 1; t < T_TOT; t++) {
        float m   = __fmul_rn(0.1f, s);
        float sum = __fmaf_rn(m, s, s);
        s = (sum >= 1.0f) ? __fadd_rn(sum, -1.0f) : sum;

        bool above = s > 0.5f;
        bool cross = above && !prev;
        prev = above;
        cnt += cross;
        if (cross) { last = t - 1; first = min(first, t - 1); }

        acc = __fadd_rn(acc, __fmul_rn(s, s));

        int bin = min(max((int)__fmul_rn(s, 20.0f), 0), 19);
        hist[bin * NTH + tid] += 1;
    }

    // ---- scalar features ----
    const float mfr = __fdiv_rn((float)cnt, 1000.0f);
    const float mft = (cnt > 1)
        ? __fdiv_rn((float)(last - first), (float)(cnt - 1))
        : 1000.0f;
    const float me = __fdiv_rn(acc, 1000.0f);

    // ---- entropy ----
    float h[NB];
    float hsum = 0.0f;
    #pragma unroll
    for (int j = 0; j < NB; j++) {
        h[j] = __fdiv_rn((float)hist[j * NTH + tid], 50.0f);
        hsum = __fadd_rn(hsum, h[j]);
    }
    const float pden = __fadd_rn(hsum, 1e-10f);
    float q[NB];
    float qsum = 0.0f;
    #pragma unroll
    for (int j = 0; j < NB; j++) {
        float p = __fdiv_rn(h[j], pden);
        q[j] = __fadd_rn(p, 1e-10f);
        qsum = __fadd_rn(qsum, q[j]);
    }
    float ment = 0.0f;
    #pragma unroll
    for (int j = 0; j < NB; j++) {
        float qq = __fdiv_rn(q[j], qsum);
        ment = __fadd_rn(ment, __fmul_rn(qq, logf(qq)));
    }
    ment = -ment;

    // ---- output: (B, N, 4) row-major ----
    float4 o;
    o.x = mft; o.y = mfr; o.z = me; o.w = ment;
    reinterpret_cast<float4*>(out)[b * NTH + tid] = o;
}

extern "C" void kernel_launch(void* const* d_in, const int* in_sizes, int n_in,
                              void* d_out, int out_size)
{
    const float* x = (const float*)d_in[0];
    float* out = (float*)d_out;
    const int B = in_sizes[0] / D_IN;   // 128
    chaosfex_kernel<<<B, NTH>>>(x, out);
}

// round 13
// speedup vs baseline: 1.0932x; 1.0932x over previous
#include <cuda_runtime.h>

#define D_IN  2048
#define T_TOT 1000
#define NB    20
#define N_NEUR 512
#define MAXROWS 512

__device__ float g_rowmin[MAXROWS];
__device__ float g_rowmax[MAXROWS];

// ---------- kernel 1: per-row min/max ----------
__global__ void __launch_bounds__(512, 1)
rowstat_kernel(const float* __restrict__ x, int nrows)
{
    __shared__ float redmin[16], redmax[16];
    const int b   = blockIdx.x;
    const int tid = threadIdx.x;
    if (b >= nrows) return;
    const float* row = x + b * D_IN;

    float v0 = row[tid], v1 = row[tid + 512], v2 = row[tid + 1024], v3 = row[tid + 1536];
    float pmin = fminf(fminf(v0, v1), fminf(v2, v3));
    float pmax = fmaxf(fmaxf(v0, v1), fmaxf(v2, v3));
    #pragma unroll
    for (int o = 16; o; o >>= 1) {
        pmin = fminf(pmin, __shfl_xor_sync(0xffffffffu, pmin, o));
        pmax = fmaxf(pmax, __shfl_xor_sync(0xffffffffu, pmax, o));
    }
    const int wid = tid >> 5, lid = tid & 31;
    if (lid == 0) { redmin[wid] = pmin; redmax[wid] = pmax; }
    __syncthreads();
    if (wid == 0) {
        float a  = redmin[lid & 15];
        float mx = redmax[lid & 15];
        #pragma unroll
        for (int o = 8; o; o >>= 1) {
            a  = fminf(a,  __shfl_xor_sync(0xffffffffu, a,  o));
            mx = fmaxf(mx, __shfl_xor_sync(0xffffffffu, mx, o));
        }
        if (lid == 0) { g_rowmin[b] = a; g_rowmax[b] = mx; }
    }
}

// ---------- kernel 2: trajectories + features, one neuron per thread ----------
__global__ void __launch_bounds__(1024, 1)
chaosfex_kernel(const float* __restrict__ x, float* __restrict__ out, int total)
{
    extern __shared__ int hist[];   // NB * blockDim.x ints, thread-private columns
    const int tid = threadIdx.x;
    const int nth = blockDim.x;
    const int g   = blockIdx.x * nth + tid;
    if (g >= total) return;

    const int row = g >> 9;          // neuron row (batch index)
    const int n   = g & (N_NEUR - 1);
    const float* xrow = x + row * D_IN;

    #pragma unroll
    for (int j = 0; j < NB; j++) hist[j * nth + tid] = 0;

    const float xmin = g_rowmin[row];
    const float xmax = g_rowmax[row];

    // ---- IC: reciprocal-multiply normalize (fast-math lowering), clip ----
    const int nidx = (n == 511) ? 2047 : (int)((double)n * (2047.0 / 511.0));
    const float xi = xrow[nidx];
    const float denomn = __fadd_rn(__fsub_rn(xmax, xmin), 1e-10f);
    const float rden  = __fdiv_rn(1.0f, denomn);
    const float xn    = __fmul_rn(__fsub_rn(xi, xmin), rden);
    float s = fminf(fmaxf(xn, 0.01f), 0.99f);

    // ---- trajectory ----
    float acc   = __fmul_rn(s, s);       // step-0 term (exact, like reference)
    int   cnt   = 0;
    int   first = 1 << 30;
    int   last  = -1;
    bool  prev  = s > 0.5f;

    hist[((int)__fmul_rn(s, 20.0f)) * nth + tid] += 1;   // s in [0.01,0.99]

    // Map B: m = rn(0.1*s); sum = fma(m,s,s); conditional wrap (exact).
    // s stays in [0,1) -> bin in [0,19], no clamp.
    #pragma unroll 9
    for (int t = 1; t < T_TOT; t++) {
        float m   = __fmul_rn(0.1f, s);
        float sum = __fmaf_rn(m, s, s);
        s = (sum >= 1.0f) ? __fadd_rn(sum, -1.0f) : sum;

        bool above = s > 0.5f;
        bool cross = above && !prev;
        prev = above;
        if (cross) { cnt++; last = t; first = min(first, t); }  // uniform +1 shift cancels in last-first

        acc = __fmaf_rn(s, s, acc);      // fused: <=1e-7 rel perturbation of ME only

        hist[((int)__fmul_rn(s, 20.0f)) * nth + tid] += 1;
    }

    // ---- scalar features ----
    const float mfr = __fdiv_rn((float)cnt, 1000.0f);
    const float mft = (cnt > 1)
        ? __fdiv_rn((float)(last - first), (float)(cnt - 1))
        : 1000.0f;
    const float me = __fdiv_rn(acc, 1000.0f);

    // ---- entropy ----
    float h[NB];
    float hsum = 0.0f;
    #pragma unroll
    for (int j = 0; j < NB; j++) {
        h[j] = __fdiv_rn((float)hist[j * nth + tid], 50.0f);
        hsum = __fadd_rn(hsum, h[j]);
    }
    const float pden = __fadd_rn(hsum, 1e-10f);
    float q[NB];
    float qsum = 0.0f;
    #pragma unroll
    for (int j = 0; j < NB; j++) {
        float p = __fdiv_rn(h[j], pden);
        q[j] = __fadd_rn(p, 1e-10f);
        qsum = __fadd_rn(qsum, q[j]);
    }
    float ment = 0.0f;
    #pragma unroll
    for (int j = 0; j < NB; j++) {
        float qq = __fdiv_rn(q[j], qsum);
        ment = __fadd_rn(ment, __fmul_rn(qq, logf(qq)));
    }
    ment = -ment;

    float4 o;
    o.x = mft; o.y = mfr; o.z = me; o.w = ment;
    reinterpret_cast<float4*>(out)[g] = o;
}

extern "C" void kernel_launch(void* const* d_in, const int* in_sizes, int n_in,
                              void* d_out, int out_size)
{
    const float* x = (const float*)d_in[0];
    float* out = (float*)d_out;
    const int B = in_sizes[0] / D_IN;          // 128
    const int total = B * N_NEUR;              // 65536

    int dev = 0, sms = 0;
    cudaGetDevice(&dev);
    cudaDeviceGetAttribute(&sms, cudaDevAttrMultiProcessorCount, dev);
    if (sms <= 0) sms = 148;

    // one block per SM: nth = ceil(total/sms) rounded up to a warp, capped at 1024
    int nth = (total + sms - 1) / sms;
    nth = (nth + 31) & ~31;
    if (nth > 1024) nth = 1024;
    if (nth < 32)  nth = 32;
    const int grid = (total + nth - 1) / nth;
    const size_t smem = (size_t)NB * nth * sizeof(int);

    cudaFuncSetAttribute(chaosfex_kernel,
                         cudaFuncAttributeMaxDynamicSharedMemorySize, (int)(NB * 1024 * sizeof(int)));

    rowstat_kernel<<<B, 512>>>(x, B);
    chaosfex_kernel<<<grid, nth, smem>>>(x, out, total);
}